// round 15
// baseline (speedup 1.0000x reference)
#include <cuda_runtime.h>
#include <cuda_bf16.h>

// Problem constants
#define N_WORKER   1807
#define N_PROJECT  2490
#define EMB        10
#define STATE_DIM  20
#define HIDDEN     40
#define NCAND      2489        // candidates = project_emb rows 1..2489 (cand c -> row c+1)
#define BATCH      65536

#define NSPLIT     13
#define SPLIT_CAND 192         // 13*192 = 2496 >= 2489; overflow slots clamp to cand 2488
#define THREADS    128
#define SPT        4           // samples per thread in actor
#define SBLK       (BATCH / (THREADS * SPT))   // 128 sample blocks
#define ACTOR_CTAS (SBLK * NSPLIT)             // 1664 CTAs @4/SM resident

#define W2T_PITCH  12          // padded transposed-W2 row (48B, 16-aligned)

// MLP shape: 1 warp per CTA, 2 samples per thread
#define MLP_THREADS 32
#define MLP_SPT     2
#define MLP_CTAS    (BATCH / (MLP_THREADS * MLP_SPT))   // 1024

// per-sample action weights (plain floats; actor packs sample-pairs)
__device__ float g_w[BATCH][EMB];
// per-sample global argmax accumulator: (ord(val) << 32) | (NCAND - idx)
__device__ unsigned long long g_best[BATCH];

// ---- packed f32x2 helpers (sm_103a FFMA2 path) ----
__device__ __forceinline__ unsigned long long pack2(float lo, float hi) {
    unsigned long long r;
    asm("mov.b64 %0, {%1, %2};" : "=l"(r) : "f"(lo), "f"(hi));
    return r;
}
__device__ __forceinline__ void unpack2(unsigned long long v, float& lo, float& hi) {
    asm("mov.b64 {%0, %1}, %2;" : "=f"(lo), "=f"(hi) : "l"(v));
}
__device__ __forceinline__ unsigned long long fmul2(unsigned long long a, unsigned long long b) {
    unsigned long long d;
    asm("mul.rn.f32x2 %0, %1, %2;" : "=l"(d) : "l"(a), "l"(b));
    return d;
}
__device__ __forceinline__ unsigned long long ffma2(unsigned long long a, unsigned long long b,
                                                    unsigned long long c) {
    unsigned long long d;
    asm("fma.rn.f32x2 %0, %1, %2, %3;" : "=l"(d) : "l"(a), "l"(b), "l"(c));
    return d;
}

// order-preserving float->u32: f1 > f2  <=>  ord(f1) > ord(f2)  (finite floats)
__device__ __forceinline__ unsigned int ord_encode(float f) {
    unsigned int b = __float_as_uint(f);
    return ((int)b < 0) ? ~b : (b | 0x80000000u);
}

__device__ __forceinline__ int load_id(const void* p, int i, int ids64) {
    return ids64 ? (int)((const long long*)p)[i] : ((const int*)p)[i];
}

// ---- MLP kernel: 1 warp/CTA, 2 full samples per thread ----
// Weight LDS amortized over both samples (crossbar traffic halved vs R13/14).
__global__ __launch_bounds__(MLP_THREADS)
void mlp_kernel(const void* __restrict__ idA,
                const void* __restrict__ idB,
                const float* __restrict__ worker_emb,
                const float* __restrict__ project_emb,
                const float* __restrict__ W1,
                const float* __restrict__ b1,
                const float* __restrict__ W2,
                const float* __restrict__ b2)
{
    __shared__ __align__(16) float sW1[HIDDEN * STATE_DIM];   // [k][j], 80B rows
    __shared__ __align__(16) float sW2t[HIDDEN * W2T_PITCH];  // [k][d], 48B rows
    __shared__ float sb1[HIDDEN];
    __shared__ float sb2[EMB];

    const int tid = threadIdx.x;

    // -- warp-local id-layout detection (128 sampled u64-slots; P[err] < e^-41) --
    int ids64, swap;
    {
        const unsigned int* a32 = (const unsigned int*)idA;
        const unsigned int* b32 = (const unsigned int*)idB;
        unsigned int odd_or = 0, even_mx = 0;
        #pragma unroll
        for (int k = 0; k < 4; k++) {
            const int i = (tid + k * 32) * (BATCH / 512);
            odd_or  |= a32[2 * i + 1] | b32[2 * i + 1];
            even_mx  = max(even_mx, a32[2 * i]);
        }
        #pragma unroll
        for (int o = 16; o > 0; o >>= 1) {
            odd_or  |= __shfl_xor_sync(0xffffffffu, odd_or, o);
            even_mx  = max(even_mx, __shfl_xor_sync(0xffffffffu, even_mx, o));
        }
        ids64 = (odd_or == 0) ? 1 : 0;
        swap  = (even_mx >= (unsigned)N_WORKER) ? 1 : 0;
    }

    // -- stage weights (single warp) --
    {
        const float4* W1v = reinterpret_cast<const float4*>(W1);
        float4* sW1v = reinterpret_cast<float4*>(sW1);
        #pragma unroll
        for (int i = tid; i < (HIDDEN * STATE_DIM) / 4; i += MLP_THREADS)
            sW1v[i] = __ldg(W1v + i);
        for (int i = tid; i < HIDDEN * EMB; i += MLP_THREADS) {
            const int d = i / HIDDEN;
            const int k = i - d * HIDDEN;
            sW2t[k * W2T_PITCH + d] = __ldg(W2 + i);
        }
        for (int i = tid; i < HIDDEN; i += MLP_THREADS) sb1[i] = __ldg(b1 + i);
        if (tid < EMB) sb2[tid] = __ldg(b2 + tid);
    }
    __syncwarp();

    const void* worker_ids  = swap ? idB : idA;
    const void* project_ids = swap ? idA : idB;

    // two samples per thread: g, g+32 (coalesced)
    int gg[MLP_SPT];
    float x[MLP_SPT][STATE_DIM];
    #pragma unroll
    for (int s = 0; s < MLP_SPT; s++) {
        gg[s] = blockIdx.x * (MLP_THREADS * MLP_SPT) + s * MLP_THREADS + tid;
        const int wi = load_id(worker_ids,  gg[s], ids64);
        const int pi = load_id(project_ids, gg[s], ids64);
        const float2* wrow = reinterpret_cast<const float2*>(worker_emb + wi * EMB);
        const float2* prow = reinterpret_cast<const float2*>(project_emb + pi * EMB);
        #pragma unroll
        for (int j = 0; j < 5; j++) {
            const float2 v = __ldg(wrow + j);
            x[s][2 * j] = v.x; x[s][2 * j + 1] = v.y;
        }
        #pragma unroll
        for (int j = 0; j < 5; j++) {
            const float2 v = __ldg(prow + j);
            x[s][EMB + 2 * j] = v.x; x[s][EMB + 2 * j + 1] = v.y;
        }
    }

    float a[MLP_SPT][EMB];
    #pragma unroll
    for (int s = 0; s < MLP_SPT; s++)
        #pragma unroll
        for (int d = 0; d < EMB; d++) a[s][d] = sb2[d];

    // hidden units 2 at a time; each weight load serves both samples
    #pragma unroll 2
    for (int k0 = 0; k0 < HIDDEN; k0 += 2) {
        const float4* r0 = reinterpret_cast<const float4*>(sW1 + k0 * STATE_DIM);
        const float4* r1 = reinterpret_cast<const float4*>(sW1 + (k0 + 1) * STATE_DIM);
        float h[MLP_SPT][2];
        #pragma unroll
        for (int s = 0; s < MLP_SPT; s++) { h[s][0] = sb1[k0]; h[s][1] = sb1[k0 + 1]; }
        #pragma unroll
        for (int q4 = 0; q4 < 5; q4++) {
            const float4 w0 = r0[q4];
            const float4 w1 = r1[q4];
            const int j = q4 * 4;
            #pragma unroll
            for (int s = 0; s < MLP_SPT; s++) {
                h[s][0] += w0.x * x[s][j]     + w0.y * x[s][j + 1]
                         + w0.z * x[s][j + 2] + w0.w * x[s][j + 3];
                h[s][1] += w1.x * x[s][j]     + w1.y * x[s][j + 1]
                         + w1.z * x[s][j + 2] + w1.w * x[s][j + 3];
            }
        }
        const float4* c0 = reinterpret_cast<const float4*>(sW2t + k0 * W2T_PITCH);
        const float4* c1 = reinterpret_cast<const float4*>(sW2t + (k0 + 1) * W2T_PITCH);
        const float4 u0 = c0[0], u1 = c0[1], u2 = c0[2];
        const float4 v0 = c1[0], v1 = c1[1], v2 = c1[2];
        #pragma unroll
        for (int s = 0; s < MLP_SPT; s++) {
            const float h0 = fmaxf(h[s][0], 0.0f);
            const float h1 = fmaxf(h[s][1], 0.0f);
            a[s][0] += u0.x * h0 + v0.x * h1;
            a[s][1] += u0.y * h0 + v0.y * h1;
            a[s][2] += u0.z * h0 + v0.z * h1;
            a[s][3] += u0.w * h0 + v0.w * h1;
            a[s][4] += u1.x * h0 + v1.x * h1;
            a[s][5] += u1.y * h0 + v1.y * h1;
            a[s][6] += u1.z * h0 + v1.z * h1;
            a[s][7] += u1.w * h0 + v1.w * h1;
            a[s][8] += u2.x * h0 + v2.x * h1;
            a[s][9] += u2.y * h0 + v2.y * h1;
        }
    }

    #pragma unroll
    for (int s = 0; s < MLP_SPT; s++) {
        float2* wrow_out = reinterpret_cast<float2*>(g_w[gg[s]]);
        #pragma unroll
        for (int j = 0; j < 5; j++)
            wrow_out[j] = make_float2(a[s][2 * j], a[s][2 * j + 1]);
        g_best[gg[s]] = 0ULL;   // init for actor's atomicMax (every packed value > 0)
    }
}

// ---- actor: sample-pair packed dots; atomicMax merge epilogue ----
__global__ __launch_bounds__(THREADS, 4)
void actor_kernel(const float* __restrict__ project_emb)
{
    // duplicated-pair table: tbl[c*10 + j] = (t_c[j], t_c[j]); 15360 B
    __shared__ __align__(16) unsigned long long tbl[SPLIT_CAND * EMB];

    const int split = blockIdx.x % NSPLIT;
    const int sblk  = blockIdx.x / NSPLIT;
    const int c0    = split * SPLIT_CAND;     // global candidate base
    const int tid   = threadIdx.x;

    // stage duplicated pairs; overflow slots CLAMP to candidate NCAND-1
    // (duplicates are exact; strict '>' in ascending order keeps the first = real slot)
    for (int e = tid; e < SPLIT_CAND * EMB; e += THREADS) {
        const int c = e / EMB;
        const int j = e - c * EMB;
        const int ci = min(c0 + c, NCAND - 1);
        const float t = __ldg(project_emb + (ci + 1) * EMB + j);
        tbl[e] = pack2(t, t);
    }

    // per-thread: 4 samples -> 2 sample-pair packed weight vectors (40 regs)
    int g[SPT];
    unsigned long long wd01[EMB], wd23[EMB];
    {
        float aw[SPT][EMB];
        #pragma unroll
        for (int s = 0; s < SPT; s++) {
            g[s] = (sblk * SPT + s) * THREADS + tid;
            const float2* wr = reinterpret_cast<const float2*>(g_w[g[s]]);
            #pragma unroll
            for (int j = 0; j < 5; j++) {
                const float2 v = __ldg(wr + j);
                aw[s][2 * j] = v.x; aw[s][2 * j + 1] = v.y;
            }
        }
        #pragma unroll
        for (int j = 0; j < EMB; j++) {
            wd01[j] = pack2(aw[0][j], aw[1][j]);
            wd23[j] = pack2(aw[2][j], aw[3][j]);
        }
    }
    __syncthreads();

    float bv[SPT];
    int   bc[SPT];
    #pragma unroll
    for (int s = 0; s < SPT; s++) { bv[s] = __int_as_float(0xff800000); bc[s] = 0; }

    const ulonglong2* q = reinterpret_cast<const ulonglong2*>(tbl);
    #pragma unroll 2
    for (int c = 0; c < SPLIT_CAND; c++) {
        const ulonglong2 q0 = q[c * 5 + 0];   // dims 0,1 (each duplicated)
        const ulonglong2 q1 = q[c * 5 + 1];   // dims 2,3
        const ulonglong2 q2 = q[c * 5 + 2];   // dims 4,5
        const ulonglong2 q3 = q[c * 5 + 3];   // dims 6,7
        const ulonglong2 q4 = q[c * 5 + 4];   // dims 8,9

        unsigned long long a01 = fmul2(wd01[0], q0.x);
        unsigned long long a23 = fmul2(wd23[0], q0.x);
        a01 = ffma2(wd01[1], q0.y, a01);  a23 = ffma2(wd23[1], q0.y, a23);
        a01 = ffma2(wd01[2], q1.x, a01);  a23 = ffma2(wd23[2], q1.x, a23);
        a01 = ffma2(wd01[3], q1.y, a01);  a23 = ffma2(wd23[3], q1.y, a23);
        a01 = ffma2(wd01[4], q2.x, a01);  a23 = ffma2(wd23[4], q2.x, a23);
        a01 = ffma2(wd01[5], q2.y, a01);  a23 = ffma2(wd23[5], q2.y, a23);
        a01 = ffma2(wd01[6], q3.x, a01);  a23 = ffma2(wd23[6], q3.x, a23);
        a01 = ffma2(wd01[7], q3.y, a01);  a23 = ffma2(wd23[7], q3.y, a23);
        a01 = ffma2(wd01[8], q4.x, a01);  a23 = ffma2(wd23[8], q4.x, a23);
        a01 = ffma2(wd01[9], q4.y, a01);  a23 = ffma2(wd23[9], q4.y, a23);

        float d[SPT];
        unpack2(a01, d[0], d[1]);
        unpack2(a23, d[2], d[3]);
        #pragma unroll
        for (int s = 0; s < SPT; s++) {
            const bool gt = (d[s] > bv[s]);   // ascending c + strict '>' = first max
            bv[s] = gt ? d[s] : bv[s];
            bc[s] = gt ? c    : bc[s];
        }
    }

    // atomic merge: larger val wins; on equal val, larger (NCAND-idx) = smaller idx wins
    #pragma unroll
    for (int s = 0; s < SPT; s++) {
        const int gidx = min(c0 + bc[s], NCAND - 1);
        const unsigned long long packed =
            ((unsigned long long)ord_encode(bv[s]) << 32) |
            (unsigned int)(NCAND - gidx);
        atomicMax(&g_best[g[s]], packed);
    }
}

// ---- decode: packed best -> float index ----
__global__ void out_kernel(float* __restrict__ out)
{
    const int i = blockIdx.x * 256 + threadIdx.x;
    const unsigned long long p = g_best[i];
    const int idx = NCAND - (int)(p & 0xffffffffu);
    out[i] = (float)(idx + 1);
}

extern "C" void kernel_launch(void* const* d_in, const int* in_sizes, int n_in,
                              void* d_out, int out_size)
{
    // Order-proof binding: every float array has a unique element count.
    const void*  idA = nullptr;
    const void*  idB = nullptr;
    const float* worker_emb  = nullptr;  // 18070
    const float* project_emb = nullptr;  // 24900
    const float* W1 = nullptr;           // 800
    const float* b1 = nullptr;           // 40
    const float* W2 = nullptr;           // 400
    const float* b2 = nullptr;           // 10

    for (int i = 0; i < n_in; i++) {
        switch (in_sizes[i]) {
            case BATCH: if (!idA) idA = d_in[i];
                        else      idB = d_in[i];                      break;
            case 18070: worker_emb  = (const float*)d_in[i];          break;
            case 24900: project_emb = (const float*)d_in[i];          break;
            case 800:   W1 = (const float*)d_in[i];                   break;
            case 40:    b1 = (const float*)d_in[i];                   break;
            case 400:   W2 = (const float*)d_in[i];                   break;
            case 10:    b2 = (const float*)d_in[i];                   break;
            default: break;
        }
    }

    mlp_kernel<<<MLP_CTAS, MLP_THREADS>>>(idA, idB, worker_emb, project_emb,
                                          W1, b1, W2, b2);
    actor_kernel<<<ACTOR_CTAS, THREADS>>>(project_emb);
    out_kernel<<<BATCH / 256, 256>>>((float*)d_out);
}